// round 4
// baseline (speedup 1.0000x reference)
#include <cuda_runtime.h>
#include <cuda_bf16.h>

#define BATCH 64
#define CHANS 3
#define HH 384
#define WW 384
#define HW (HH * WW)

#define TX 32          // tile cols
#define TY 8           // tile rows
#define WCAP 64        // max window cols
#define HCAP 20        // max window rows
#define WSTRIDE 65     // odd stride -> conflict-free LDS
#define CHSTRIDE (HCAP * WSTRIDE)

__global__ __launch_bounds__(256)
void affine_kernel(const float* __restrict__ imgs,
                   const float* __restrict__ theta,
                   float* __restrict__ out) {
    __shared__ float sm[CHANS * CHSTRIDE];

    const int tid  = threadIdx.x;
    const int lane = tid & 31;
    const int wid  = tid >> 5;

    const int c0 = blockIdx.x * TX;      // tile origin col
    const int r0 = blockIdx.y * TY;      // tile origin row
    const int b  = blockIdx.z;

    const int col = c0 + lane;
    const int row = r0 + wid;

    const float* th = theta + b * 6;
    const float t00 = __ldg(th + 0);
    const float t01 = __ldg(th + 1);
    const float t02 = __ldg(th + 2);
    const float t10 = __ldg(th + 3);
    const float t11 = __ldg(th + 4);
    const float t12 = __ldg(th + 5);
    const float bx = t02 + 191.5f;
    const float by = t12 + 191.5f;

    // per-pixel sample coords
    const float xc = (float)col - 191.5f;
    const float yc = (float)row - 191.5f;
    const float ix = fmaf(t00, xc, fmaf(t01, yc, bx));
    const float iy = fmaf(t10, xc, fmaf(t11, yc, by));

    // tile-corner extents (affine -> extrema at corners); block-uniform
    const float xa = (float)c0 - 191.5f;
    const float xb = (float)(c0 + TX - 1) - 191.5f;
    const float ya = (float)r0 - 191.5f;
    const float yb = (float)(r0 + TY - 1) - 191.5f;

    const float ix00 = fmaf(t00, xa, fmaf(t01, ya, bx));
    const float ix10 = fmaf(t00, xb, fmaf(t01, ya, bx));
    const float ix01 = fmaf(t00, xa, fmaf(t01, yb, bx));
    const float ix11 = fmaf(t00, xb, fmaf(t01, yb, bx));
    const float iy00 = fmaf(t10, xa, fmaf(t11, ya, by));
    const float iy10 = fmaf(t10, xb, fmaf(t11, ya, by));
    const float iy01 = fmaf(t10, xa, fmaf(t11, yb, by));
    const float iy11 = fmaf(t10, xb, fmaf(t11, yb, by));

    const float ixmn = fminf(fminf(ix00, ix10), fminf(ix01, ix11));
    const float ixmx = fmaxf(fmaxf(ix00, ix10), fmaxf(ix01, ix11));
    const float iymn = fminf(fminf(iy00, iy10), fminf(iy01, iy11));
    const float iymx = fmaxf(fmaxf(iy00, iy10), fmaxf(iy01, iy11));

    // window with +-1 margin against fma rounding skew; +1 for the bilinear tap
    const int xmin = __float2int_rd(ixmn) - 1;
    const int ymin = __float2int_rd(iymn) - 1;
    const int w = __float2int_rd(ixmx) + 2 - xmin + 1;
    const int h = __float2int_rd(iymx) + 2 - ymin + 1;

    // bilinear setup (shared by both paths)
    const int x0 = __float2int_rd(ix);
    const int y0 = __float2int_rd(iy);
    const float wx1 = ix - (float)x0;
    const float wy1 = iy - (float)y0;
    const float wx0 = 1.0f - wx1;
    const float wy0 = 1.0f - wy1;
    const float w00 = wx0 * wy0;
    const float w10 = wx1 * wy0;
    const float w01 = wx0 * wy1;
    const float w11 = wx1 * wy1;

    const float* img = imgs + (size_t)b * (CHANS * HW);
    float* op = out + (size_t)b * (CHANS * HW) + row * WW + col;

    if (w <= WCAP && h <= HCAP) {
        // ---- fast path: stage window in smem, gather via LDS ----
        const bool win_inside = (xmin >= 0) & (xmin + w <= WW) &
                                (ymin >= 0) & (ymin + h <= HH);
        if (win_inside) {
            // pure coalesced fill, no predicates
#pragma unroll
            for (int ch = 0; ch < CHANS; ch++) {
                const float* pc = img + ch * HW + ymin * WW + xmin;
                float* sc = sm + ch * CHSTRIDE;
#pragma unroll 1
                for (int r = wid; r < h; r += 8) {
                    const float* prow = pc + r * WW;
                    float* srow = sc + r * WSTRIDE;
                    for (int c = lane; c < w; c += 32)
                        srow[c] = __ldg(prow + c);
                }
            }
        } else {
            // border block: zero-fill out-of-image cells
#pragma unroll
            for (int ch = 0; ch < CHANS; ch++) {
                const float* pc = img + ch * HW;
                float* sc = sm + ch * CHSTRIDE;
#pragma unroll 1
                for (int r = wid; r < h; r += 8) {
                    const int gy = ymin + r;
                    const bool rowok = ((unsigned)gy < (unsigned)HH);
                    const float* prow = pc + gy * WW;
                    float* srow = sc + r * WSTRIDE;
                    for (int c = lane; c < w; c += 32) {
                        const int gx = xmin + c;
                        float v = 0.0f;
                        if (rowok & ((unsigned)gx < (unsigned)WW))
                            v = __ldg(prow + gx);
                        srow[c] = v;
                    }
                }
            }
        }
        __syncthreads();

        const int si = (y0 - ymin) * WSTRIDE + (x0 - xmin);
        float v00[CHANS], v10[CHANS], v01[CHANS], v11[CHANS];
#pragma unroll
        for (int ch = 0; ch < CHANS; ch++) {
            const float* sc = sm + ch * CHSTRIDE + si;
            v00[ch] = sc[0];
            v10[ch] = sc[1];
            v01[ch] = sc[WSTRIDE];
            v11[ch] = sc[WSTRIDE + 1];
        }
#pragma unroll
        for (int ch = 0; ch < CHANS; ch++) {
            float acc = v00[ch] * w00;
            acc = fmaf(v10[ch], w10, acc);
            acc = fmaf(v01[ch], w01, acc);
            acc = fmaf(v11[ch], w11, acc);
            op[ch * HW] = acc;
        }
    } else {
        // ---- fallback (pathological theta): per-pixel global gathers ----
        const int x1 = x0 + 1;
        const int y1 = y0 + 1;
        const float vx0 = ((unsigned)x0 < (unsigned)WW) ? 1.0f : 0.0f;
        const float vx1 = ((unsigned)x1 < (unsigned)WW) ? 1.0f : 0.0f;
        const float vy0 = ((unsigned)y0 < (unsigned)HH) ? 1.0f : 0.0f;
        const float vy1 = ((unsigned)y1 < (unsigned)HH) ? 1.0f : 0.0f;

        const float m00 = w00 * (vx0 * vy0);
        const float m10 = w10 * (vx1 * vy0);
        const float m01 = w01 * (vx0 * vy1);
        const float m11 = w11 * (vx1 * vy1);

        const int x0c = min(max(x0, 0), WW - 1);
        const int x1c = min(max(x1, 0), WW - 1);
        const int y0c = min(max(y0, 0), HH - 1);
        const int y1c = min(max(y1, 0), HH - 1);

        const int o00 = y0c * WW + x0c;
        const int o10 = y0c * WW + x1c;
        const int o01 = y1c * WW + x0c;
        const int o11 = y1c * WW + x1c;

        float v00[CHANS], v10[CHANS], v01[CHANS], v11[CHANS];
#pragma unroll
        for (int ch = 0; ch < CHANS; ch++) {
            const float* pc = img + ch * HW;
            v00[ch] = __ldg(pc + o00);
            v10[ch] = __ldg(pc + o10);
            v01[ch] = __ldg(pc + o01);
            v11[ch] = __ldg(pc + o11);
        }
#pragma unroll
        for (int ch = 0; ch < CHANS; ch++) {
            float acc = v00[ch] * m00;
            acc = fmaf(v10[ch], m10, acc);
            acc = fmaf(v01[ch], m01, acc);
            acc = fmaf(v11[ch], m11, acc);
            op[ch * HW] = acc;
        }
    }
}

extern "C" void kernel_launch(void* const* d_in, const int* in_sizes, int n_in,
                              void* d_out, int out_size) {
    const float* imgs  = (const float*)d_in[0];
    const float* theta = (const float*)d_in[1];
    float* out = (float*)d_out;

    dim3 block(256);
    dim3 grid(WW / TX, HH / TY, BATCH);  // 12 x 48 x 64
    affine_kernel<<<grid, block>>>(imgs, theta, out);
}

// round 6
// speedup vs baseline: 2.1163x; 2.1163x over previous
#include <cuda_runtime.h>
#include <cuda_bf16.h>

#define BATCH 64
#define CHANS 3
#define HH 384
#define WW 384
#define HW (HH * WW)

#define TX 32           // tile cols
#define TY 8            // tile rows
#define FW 48           // fixed window cols
#define FH 16           // fixed window rows
#define SSTRIDE 49      // odd -> conflict-free LDS
#define CHSTRIDE (FH * SSTRIDE)   // 784

__global__ __launch_bounds__(256)
void affine_kernel(const float* __restrict__ imgs,
                   const float* __restrict__ theta,
                   float* __restrict__ out) {
    __shared__ float sm[CHANS * CHSTRIDE];   // 9408 B

    const int tid  = threadIdx.x;
    const int lane = tid & 31;
    const int wid  = tid >> 5;

    const int c0 = blockIdx.x * TX;
    const int r0 = blockIdx.y * TY;
    const int b  = blockIdx.z;

    const int col = c0 + lane;
    const int row = r0 + wid;

    const float* th = theta + b * 6;
    const float t00 = __ldg(th + 0);
    const float t01 = __ldg(th + 1);
    const float t02 = __ldg(th + 2);
    const float t10 = __ldg(th + 3);
    const float t11 = __ldg(th + 4);
    const float t12 = __ldg(th + 5);
    const float bx = t02 + 191.5f;
    const float by = t12 + 191.5f;

    // per-pixel sample coords
    const float xc = (float)col - 191.5f;
    const float yc = (float)row - 191.5f;
    const float ix = fmaf(t00, xc, fmaf(t01, yc, bx));
    const float iy = fmaf(t10, xc, fmaf(t11, yc, by));

    // block-uniform tile-corner extents
    const float xa = (float)c0 - 191.5f;
    const float xb = (float)(c0 + TX - 1) - 191.5f;
    const float ya = (float)r0 - 191.5f;
    const float yb = (float)(r0 + TY - 1) - 191.5f;

    const float ix00 = fmaf(t00, xa, fmaf(t01, ya, bx));
    const float ix10 = fmaf(t00, xb, fmaf(t01, ya, bx));
    const float ix01 = fmaf(t00, xa, fmaf(t01, yb, bx));
    const float ix11 = fmaf(t00, xb, fmaf(t01, yb, bx));
    const float iy00 = fmaf(t10, xa, fmaf(t11, ya, by));
    const float iy10 = fmaf(t10, xb, fmaf(t11, ya, by));
    const float iy01 = fmaf(t10, xa, fmaf(t11, yb, by));
    const float iy11 = fmaf(t10, xb, fmaf(t11, yb, by));

    const float ixmn = fminf(fminf(ix00, ix10), fminf(ix01, ix11));
    const float ixmx = fmaxf(fmaxf(ix00, ix10), fmaxf(ix01, ix11));
    const float iymn = fminf(fminf(iy00, iy10), fminf(iy01, iy11));
    const float iymx = fmaxf(fmaxf(iy00, iy10), fmaxf(iy01, iy11));

    // window origin with -1 margin; required extent (+1 tap, +1 margin each side)
    const int xmin = __float2int_rd(ixmn) - 1;
    const int ymin = __float2int_rd(iymn) - 1;
    const int wreq = __float2int_rd(ixmx) + 3 - xmin;   // taps <= xmin+wreq-1
    const int hreq = __float2int_rd(iymx) + 3 - ymin;

    // bilinear setup (both paths)
    const int x0 = __float2int_rd(ix);
    const int y0 = __float2int_rd(iy);
    const float wx1 = ix - (float)x0;
    const float wy1 = iy - (float)y0;
    const float wx0 = 1.0f - wx1;
    const float wy0 = 1.0f - wy1;
    const float w00 = wx0 * wy0;
    const float w10 = wx1 * wy0;
    const float w01 = wx0 * wy1;
    const float w11 = wx1 * wy1;

    const float* img = imgs + (size_t)b * (CHANS * HW);
    float* op = out + (size_t)b * (CHANS * HW) + row * WW + col;

    if (wreq <= FW && hreq <= FH) {
        // ---- fast path: static 48x16 window staged in smem ----
        // 768 cells per channel = exactly 3 per thread, fully unrolled.
        const int r0c = tid / FW,         c0c = tid - r0c * FW;
        const int r1c = (tid + 256) / FW, c1c = (tid + 256) - r1c * FW;
        const int r2c = (tid + 512) / FW, c2c = (tid + 512) - r2c * FW;
        const int goff0 = r0c * WW + c0c;
        const int goff1 = r1c * WW + c1c;
        const int goff2 = r2c * WW + c2c;
        const int soff0 = r0c * SSTRIDE + c0c;
        const int soff1 = r1c * SSTRIDE + c1c;
        const int soff2 = r2c * SSTRIDE + c2c;

        const bool win_inside = (xmin >= 0) & (xmin + FW <= WW) &
                                (ymin >= 0) & (ymin + FH <= HH);
        const float* gbase = img + ymin * WW + xmin;

        float v[9];
        if (win_inside) {
            // predicate-free, 9 independent LDGs up front (MLP=9)
#pragma unroll
            for (int ch = 0; ch < CHANS; ch++) {
                const float* g = gbase + ch * HW;
                v[ch * 3 + 0] = __ldg(g + goff0);
                v[ch * 3 + 1] = __ldg(g + goff1);
                v[ch * 3 + 2] = __ldg(g + goff2);
            }
        } else {
            const int gy0 = ymin + r0c, gx0 = xmin + c0c;
            const int gy1 = ymin + r1c, gx1 = xmin + c1c;
            const int gy2 = ymin + r2c, gx2 = xmin + c2c;
            const bool p0 = ((unsigned)gy0 < (unsigned)HH) & ((unsigned)gx0 < (unsigned)WW);
            const bool p1 = ((unsigned)gy1 < (unsigned)HH) & ((unsigned)gx1 < (unsigned)WW);
            const bool p2 = ((unsigned)gy2 < (unsigned)HH) & ((unsigned)gx2 < (unsigned)WW);
#pragma unroll
            for (int ch = 0; ch < CHANS; ch++) {
                const float* g = gbase + ch * HW;
                float a0 = 0.0f, a1 = 0.0f, a2 = 0.0f;
                if (p0) a0 = __ldg(g + goff0);
                if (p1) a1 = __ldg(g + goff1);
                if (p2) a2 = __ldg(g + goff2);
                v[ch * 3 + 0] = a0;
                v[ch * 3 + 1] = a1;
                v[ch * 3 + 2] = a2;
            }
        }
#pragma unroll
        for (int ch = 0; ch < CHANS; ch++) {
            float* sc = sm + ch * CHSTRIDE;
            sc[soff0] = v[ch * 3 + 0];
            sc[soff1] = v[ch * 3 + 1];
            sc[soff2] = v[ch * 3 + 2];
        }
        __syncthreads();

        const int si = (y0 - ymin) * SSTRIDE + (x0 - xmin);
        float v00[CHANS], v10[CHANS], v01[CHANS], v11[CHANS];
#pragma unroll
        for (int ch = 0; ch < CHANS; ch++) {
            const float* sc = sm + ch * CHSTRIDE + si;
            v00[ch] = sc[0];
            v10[ch] = sc[1];
            v01[ch] = sc[SSTRIDE];
            v11[ch] = sc[SSTRIDE + 1];
        }
#pragma unroll
        for (int ch = 0; ch < CHANS; ch++) {
            float acc = v00[ch] * w00;
            acc = fmaf(v10[ch], w10, acc);
            acc = fmaf(v01[ch], w01, acc);
            acc = fmaf(v11[ch], w11, acc);
            op[ch * HW] = acc;
        }
    } else {
        // ---- fallback (pathological theta): proven per-pixel gather path ----
        const int x1 = x0 + 1;
        const int y1 = y0 + 1;
        const float vx0 = ((unsigned)x0 < (unsigned)WW) ? 1.0f : 0.0f;
        const float vx1 = ((unsigned)x1 < (unsigned)WW) ? 1.0f : 0.0f;
        const float vy0 = ((unsigned)y0 < (unsigned)HH) ? 1.0f : 0.0f;
        const float vy1 = ((unsigned)y1 < (unsigned)HH) ? 1.0f : 0.0f;

        const float m00 = w00 * (vx0 * vy0);
        const float m10 = w10 * (vx1 * vy0);
        const float m01 = w01 * (vx0 * vy1);
        const float m11 = w11 * (vx1 * vy1);

        const int x0c = min(max(x0, 0), WW - 1);
        const int x1c = min(max(x1, 0), WW - 1);
        const int y0c = min(max(y0, 0), HH - 1);
        const int y1c = min(max(y1, 0), HH - 1);

        const int o00 = y0c * WW + x0c;
        const int o10 = y0c * WW + x1c;
        const int o01 = y1c * WW + x0c;
        const int o11 = y1c * WW + x1c;

        float v00[CHANS], v10[CHANS], v01[CHANS], v11[CHANS];
#pragma unroll
        for (int ch = 0; ch < CHANS; ch++) {
            const float* pc = img + ch * HW;
            v00[ch] = __ldg(pc + o00);
            v10[ch] = __ldg(pc + o10);
            v01[ch] = __ldg(pc + o01);
            v11[ch] = __ldg(pc + o11);
        }
        __syncthreads();  // keep barrier convergent with fast path
#pragma unroll
        for (int ch = 0; ch < CHANS; ch++) {
            float acc = v00[ch] * m00;
            acc = fmaf(v10[ch], m10, acc);
            acc = fmaf(v01[ch], m01, acc);
            acc = fmaf(v11[ch], m11, acc);
            op[ch * HW] = acc;
        }
    }
}

extern "C" void kernel_launch(void* const* d_in, const int* in_sizes, int n_in,
                              void* d_out, int out_size) {
    const float* imgs  = (const float*)d_in[0];
    const float* theta = (const float*)d_in[1];
    float* out = (float*)d_out;

    dim3 block(256);
    dim3 grid(WW / TX, HH / TY, BATCH);  // 12 x 48 x 64
    affine_kernel<<<grid, block>>>(imgs, theta, out);
}

// round 9
// speedup vs baseline: 3.0505x; 1.4414x over previous
#include <cuda_runtime.h>
#include <cuda_bf16.h>

#define BATCH 64
#define CHANS 3
#define HH 384
#define WW 384
#define HW (HH * WW)
#define HALF (HW / 2)   // 73728: one thread handles one column in an adjacent-row pair

__global__ __launch_bounds__(256, 3)
void affine_kernel(const float* __restrict__ imgs,
                   const float* __restrict__ theta,
                   float* __restrict__ out) {
    // pix indexes (row-pair, col): rp in [0,192), col in [0,384)
    const int pix = blockIdx.x * blockDim.x + threadIdx.x;   // < HALF, exact
    const int b = blockIdx.y;
    const int rp  = pix / WW;
    const int col = pix - rp * WW;
    const int row = rp * 2;

    const float* th = theta + b * 6;
    const float t00 = __ldg(th + 0);
    const float t01 = __ldg(th + 1);
    const float t02 = __ldg(th + 2);
    const float t10 = __ldg(th + 3);
    const float t11 = __ldg(th + 4);
    const float t12 = __ldg(th + 5);

    const float xc = (float)col - 191.5f;
    const float yc = (float)row - 191.5f;
    // pixel A = (row, col), pixel B = (row+1, col)
    const float ixA = fmaf(t00, xc, fmaf(t01, yc, t02 + 191.5f));
    const float iyA = fmaf(t10, xc, fmaf(t11, yc, t12 + 191.5f));
    const float ixB = ixA + t01;
    const float iyB = iyA + t11;

    const int x0A = __float2int_rd(ixA);
    const int y0A = __float2int_rd(iyA);
    const int x0B = __float2int_rd(ixB);
    const int y0B = __float2int_rd(iyB);

    const float wx1A = ixA - (float)x0A, wy1A = iyA - (float)y0A;
    const float wx1B = ixB - (float)x0B, wy1B = iyB - (float)y0B;
    const float wx0A = 1.0f - wx1A, wy0A = 1.0f - wy1A;
    const float wx0B = 1.0f - wx1B, wy0B = 1.0f - wy1B;

    float w00A = wx0A * wy0A, w10A = wx1A * wy0A, w01A = wx0A * wy1A, w11A = wx1A * wy1A;
    float w00B = wx0B * wy0B, w10B = wx1B * wy0B, w01B = wx0B * wy1B, w11B = wx1B * wy1B;

    const float* img = imgs + (size_t)b * (CHANS * HW);
    float* opA = out + (size_t)b * (CHANS * HW) + row * WW + col;
    float* opB = opA + WW;

    const bool intA = ((unsigned)x0A < (unsigned)(WW - 1)) & ((unsigned)y0A < (unsigned)(HH - 1));
    const bool intB = ((unsigned)x0B < (unsigned)(WW - 1)) & ((unsigned)y0B < (unsigned)(HH - 1));

    if (__all_sync(0xFFFFFFFFu, intA & intB)) {
        // fast path: one base reg per pixel, 24 LDGs batched (imm offsets) -> MLP=24
        const float* pA = img + y0A * WW + x0A;
        const float* pB = img + y0B * WW + x0B;

        float a00[CHANS], a10[CHANS], a01[CHANS], a11[CHANS];
        float b00[CHANS], b10[CHANS], b01[CHANS], b11[CHANS];
#pragma unroll
        for (int c = 0; c < CHANS; c++) {
            const float* pa = pA + c * HW;
            const float* pb = pB + c * HW;
            a00[c] = __ldg(pa);
            a10[c] = __ldg(pa + 1);
            a01[c] = __ldg(pa + WW);
            a11[c] = __ldg(pa + WW + 1);
            b00[c] = __ldg(pb);
            b10[c] = __ldg(pb + 1);
            b01[c] = __ldg(pb + WW);
            b11[c] = __ldg(pb + WW + 1);
        }
#pragma unroll
        for (int c = 0; c < CHANS; c++) {
            float accA = a00[c] * w00A;
            accA = fmaf(a10[c], w10A, accA);
            accA = fmaf(a01[c], w01A, accA);
            accA = fmaf(a11[c], w11A, accA);
            opA[c * HW] = accA;
            float accB = b00[c] * w00B;
            accB = fmaf(b10[c], w10B, accB);
            accB = fmaf(b01[c], w01B, accB);
            accB = fmaf(b11[c], w11B, accB);
            opB[c * HW] = accB;
        }
    } else {
        // generic path: clamp + validity-in-weights, both pixels
        const int x1A = x0A + 1, y1A = y0A + 1;
        const int x1B = x0B + 1, y1B = y0B + 1;

        const float vAx0 = ((unsigned)x0A < (unsigned)WW) ? 1.0f : 0.0f;
        const float vAx1 = ((unsigned)x1A < (unsigned)WW) ? 1.0f : 0.0f;
        const float vAy0 = ((unsigned)y0A < (unsigned)HH) ? 1.0f : 0.0f;
        const float vAy1 = ((unsigned)y1A < (unsigned)HH) ? 1.0f : 0.0f;
        const float vBx0 = ((unsigned)x0B < (unsigned)WW) ? 1.0f : 0.0f;
        const float vBx1 = ((unsigned)x1B < (unsigned)WW) ? 1.0f : 0.0f;
        const float vBy0 = ((unsigned)y0B < (unsigned)HH) ? 1.0f : 0.0f;
        const float vBy1 = ((unsigned)y1B < (unsigned)HH) ? 1.0f : 0.0f;

        w00A *= vAx0 * vAy0; w10A *= vAx1 * vAy0; w01A *= vAx0 * vAy1; w11A *= vAx1 * vAy1;
        w00B *= vBx0 * vBy0; w10B *= vBx1 * vBy0; w01B *= vBx0 * vBy1; w11B *= vBx1 * vBy1;

        const int x0Ac = min(max(x0A, 0), WW - 1), x1Ac = min(max(x1A, 0), WW - 1);
        const int y0Ac = min(max(y0A, 0), HH - 1), y1Ac = min(max(y1A, 0), HH - 1);
        const int x0Bc = min(max(x0B, 0), WW - 1), x1Bc = min(max(x1B, 0), WW - 1);
        const int y0Bc = min(max(y0B, 0), HH - 1), y1Bc = min(max(y1B, 0), HH - 1);

        const int oA00 = y0Ac * WW + x0Ac, oA10 = y0Ac * WW + x1Ac;
        const int oA01 = y1Ac * WW + x0Ac, oA11 = y1Ac * WW + x1Ac;
        const int oB00 = y0Bc * WW + x0Bc, oB10 = y0Bc * WW + x1Bc;
        const int oB01 = y1Bc * WW + x0Bc, oB11 = y1Bc * WW + x1Bc;

        float a00[CHANS], a10[CHANS], a01[CHANS], a11[CHANS];
        float b00[CHANS], b10[CHANS], b01[CHANS], b11[CHANS];
#pragma unroll
        for (int c = 0; c < CHANS; c++) {
            const float* pc = img + c * HW;
            a00[c] = __ldg(pc + oA00);
            a10[c] = __ldg(pc + oA10);
            a01[c] = __ldg(pc + oA01);
            a11[c] = __ldg(pc + oA11);
            b00[c] = __ldg(pc + oB00);
            b10[c] = __ldg(pc + oB10);
            b01[c] = __ldg(pc + oB01);
            b11[c] = __ldg(pc + oB11);
        }
#pragma unroll
        for (int c = 0; c < CHANS; c++) {
            float accA = a00[c] * w00A;
            accA = fmaf(a10[c], w10A, accA);
            accA = fmaf(a01[c], w01A, accA);
            accA = fmaf(a11[c], w11A, accA);
            opA[c * HW] = accA;
            float accB = b00[c] * w00B;
            accB = fmaf(b10[c], w10B, accB);
            accB = fmaf(b01[c], w01B, accB);
            accB = fmaf(b11[c], w11B, accB);
            opB[c * HW] = accB;
        }
    }
}

extern "C" void kernel_launch(void* const* d_in, const int* in_sizes, int n_in,
                              void* d_out, int out_size) {
    const float* imgs  = (const float*)d_in[0];
    const float* theta = (const float*)d_in[1];
    float* out = (float*)d_out;

    dim3 block(256);
    dim3 grid(HALF / 256, BATCH);   // 288 x 64
    affine_kernel<<<grid, block>>>(imgs, theta, out);
}